// round 8
// baseline (speedup 1.0000x reference)
#include <cuda_runtime.h>
#include <cstdint>
#include <cstddef>

#define BATCH   8192
#define IN_DIM  3072
#define HIDDEN  4096
#define OUT_DIM 10

// fc1 tiling: CTA 256x128, warp 64x64 (8 warps), BK=32, 4-stage cp.async
#define BM 256
#define BN 128
#define BK 32
#define NT (IN_DIM / BK)                  // 96 k-tiles
#define NSTAGES 4
#define A_BYTES (BM * 128)                // 32 KB (256 rows x 128B)
#define B_BYTES (BN * 128)                // 16 KB
#define STAGE_BYTES (A_BYTES + B_BYTES)   // 48 KB
#define SMEM_TOTAL (NSTAGES * STAGE_BYTES)  // 192 KB

// ---------------- device scratch (sanctioned __device__ globals) -----------
__device__ __align__(16) float g_h  [(size_t)BATCH * HIDDEN];    // hidden acts
__device__ __align__(16) float g_xr [(size_t)BATCH * IN_DIM];    // x, tf32-rounded
__device__ __align__(16) float g_w1t[(size_t)HIDDEN * IN_DIM];   // W1^T, tf32-rounded
__device__ __align__(16) float g_w2t[OUT_DIM][HIDDEN];           // W2^T

// ---------------- helpers ---------------------------------------------------
#define SW128(o) ((o) ^ ((((uint32_t)(o)) >> 3) & 0x70))

__device__ __forceinline__ uint32_t smem_u32(const void* p) {
    uint32_t a;
    asm("{ .reg .u64 t; cvta.to.shared.u64 t, %1; cvt.u32.u64 %0, t; }" : "=r"(a) : "l"(p));
    return a;
}
__device__ __forceinline__ void cp16(uint32_t s, const void* g) {
    asm volatile("cp.async.cg.shared.global [%0], [%1], 16;\n" :: "r"(s), "l"(g));
}
__device__ __forceinline__ void cp_commit() { asm volatile("cp.async.commit_group;\n"); }
__device__ __forceinline__ void cp_wait2()  { asm volatile("cp.async.wait_group 2;\n"); }

__device__ __forceinline__ float tf32r(float f) {   // round-to-nearest tf32
    uint32_t u;
    asm("cvt.rna.tf32.f32 %0, %1;" : "=r"(u) : "f"(f));
    return __uint_as_float(u);
}

#define LDSM4(r0, r1, r2, r3, addr) \
    asm volatile("ldmatrix.sync.aligned.m8n8.x4.shared.b16 {%0,%1,%2,%3}, [%4];" \
                 : "=r"(r0), "=r"(r1), "=r"(r2), "=r"(r3) : "r"(addr))

__device__ __forceinline__ void mma_tf32(float& c0, float& c1, float& c2, float& c3,
                                         uint32_t a0, uint32_t a1, uint32_t a2, uint32_t a3,
                                         uint32_t b0, uint32_t b1) {
    asm volatile(
        "mma.sync.aligned.m16n8k8.row.col.f32.tf32.tf32.f32 "
        "{%0,%1,%2,%3}, {%4,%5,%6,%7}, {%8,%9}, {%0,%1,%2,%3};\n"
        : "+f"(c0), "+f"(c1), "+f"(c2), "+f"(c3)
        : "r"(a0), "r"(a1), "r"(a2), "r"(a3), "r"(b0), "r"(b1));
}

// ---------------------------------------------------------------------------
// Pre-pass 1: x -> g_xr rounded to tf32 (in-loop CVTs eliminated; exact HMMA)
// ---------------------------------------------------------------------------
__global__ __launch_bounds__(256) void xr_kernel(const float* __restrict__ x) {
    const size_t i = (size_t)blockIdx.x * 256 + threadIdx.x;   // float4 index
    const float4 v = ((const float4*)x)[i];
    float4 o;
    o.x = tf32r(v.x); o.y = tf32r(v.y); o.z = tf32r(v.z); o.w = tf32r(v.w);
    ((float4*)g_xr)[i] = o;
}

// ---------------------------------------------------------------------------
// Pre-pass 2: W1 [K][N] -> g_w1t [N][K], tf32-rounded. Tiled transpose.
// ---------------------------------------------------------------------------
__global__ __launch_bounds__(256) void w1t_kernel(const float* __restrict__ W1) {
    __shared__ float t[32][33];
    const int n0 = blockIdx.x * 32, k0 = blockIdx.y * 32;
    const int tx = threadIdx.x, ty = threadIdx.y;
    #pragma unroll
    for (int i = ty; i < 32; i += 8)
        t[i][tx] = W1[(size_t)(k0 + i) * HIDDEN + n0 + tx];
    __syncthreads();
    #pragma unroll
    for (int i = ty; i < 32; i += 8)
        g_w1t[(size_t)(n0 + i) * IN_DIM + k0 + tx] = tf32r(t[tx][i]);
}

// ---------------------------------------------------------------------------
// fc1: h = relu(xr @ w1t^T + b1), legacy tf32 mma.sync + ldmatrix + cp.async.
// Single-barrier multistage pipeline: one __syncthreads per k-tile; loads for
// tile kt+3 are issued right after the barrier (into the stage freed by it).
// ---------------------------------------------------------------------------
__global__ __launch_bounds__(256, 1) void fc1_mma_kernel(const float* __restrict__ b1)
{
    extern __shared__ __align__(1024) char smem[];
    const uint32_t smem_base = smem_u32(smem);

    const int tid  = (int)threadIdx.x;
    const int warp = tid >> 5, lane = tid & 31;
    const int grp  = lane >> 2, tig = lane & 3;
    const int wm   = (warp >> 1) * 64;     // 4 warps along M
    const int wn   = (warp & 1) * 64;      // 2 warps along N
    const int bm0  = blockIdx.y * BM;
    const int bn0  = blockIdx.x * BN;

    // per-lane ldmatrix address components
    const int aRow = (lane & 7) + ((lane >> 3) & 1) * 8;   // A: m0/m1 row pairs
    const int aByt = (lane >> 4) * 16;                      // A: k, k+4 halves
    const int bRow = ((lane >> 4) & 1) * 8 + (lane & 7);    // B: n 0-7 / 8-15
    const int bByt = ((lane >> 3) & 1) * 16;                // B: k, k+4 halves

    float c[4][8][4];
    #pragma unroll
    for (int mi = 0; mi < 4; mi++)
        #pragma unroll
        for (int ni = 0; ni < 8; ni++)
            #pragma unroll
            for (int r = 0; r < 4; r++) c[mi][ni][r] = 0.f;

    // --- stage loader: A 2048 + B 1024 16B-chunks, 12 per thread ------------
    auto load_tile = [&](int kt, int s) {
        const uint32_t sA = smem_base + s * STAGE_BYTES;
        const uint32_t sB = sA + A_BYTES;
        const float* gx = g_xr  + (size_t)bm0 * IN_DIM + kt * BK;
        const float* gw = g_w1t + (size_t)bn0 * IN_DIM + kt * BK;
        #pragma unroll
        for (int i = 0; i < 8; i++) {
            const int cidx = tid + i * 256;
            const int row = cidx >> 3, col = cidx & 7;
            cp16(sA + SW128(row * 128 + col * 16), gx + (size_t)row * IN_DIM + col * 4);
        }
        #pragma unroll
        for (int i = 0; i < 4; i++) {
            const int cidx = tid + i * 256;
            const int row = cidx >> 3, col = cidx & 7;
            cp16(sB + SW128(row * 128 + col * 16), gw + (size_t)row * IN_DIM + col * 4);
        }
        cp_commit();
    };

    // prologue: 3 tiles in flight
    load_tile(0, 0);
    load_tile(1, 1);
    load_tile(2, 2);

    for (int kt = 0; kt < NT; kt++) {
        const int s = kt & 3;
        cp_wait2();          // tile kt's group complete (<=2 newer pending)
        __syncthreads();     // data visible to all warps; also proves all warps
                             // finished tile kt-1 => stage (kt-1)&3 is free

        if (kt + 3 < NT) load_tile(kt + 3, (kt + 3) & 3);  // == stage (kt-1)&3

        const uint32_t sA = smem_base + s * STAGE_BYTES;
        const uint32_t sB = sA + A_BYTES;

        #pragma unroll
        for (int step = 0; step < 4; step++) {
            const int kb = step * 32;
            uint32_t a[4][4], b[8][2];
            #pragma unroll
            for (int mi = 0; mi < 4; mi++) {
                const uint32_t ad = sA + SW128((wm + mi * 16 + aRow) * 128 + kb + aByt);
                LDSM4(a[mi][0], a[mi][1], a[mi][2], a[mi][3], ad);
            }
            #pragma unroll
            for (int nj = 0; nj < 4; nj++) {
                const uint32_t bd = sB + SW128((wn + nj * 16 + bRow) * 128 + kb + bByt);
                LDSM4(b[2 * nj][0], b[2 * nj][1], b[2 * nj + 1][0], b[2 * nj + 1][1], bd);
            }
            #pragma unroll
            for (int mi = 0; mi < 4; mi++)
                #pragma unroll
                for (int ni = 0; ni < 8; ni++)
                    mma_tf32(c[mi][ni][0], c[mi][ni][1], c[mi][ni][2], c[mi][ni][3],
                             a[mi][0], a[mi][1], a[mi][2], a[mi][3],
                             b[ni][0], b[ni][1]);
        }
    }

    // epilogue: bias + relu, float2 stores
    float bx[8], by[8];
    #pragma unroll
    for (int ni = 0; ni < 8; ni++) {
        const int col = bn0 + wn + ni * 8 + tig * 2;
        bx[ni] = __ldg(b1 + col);
        by[ni] = __ldg(b1 + col + 1);
    }
    #pragma unroll
    for (int mi = 0; mi < 4; mi++) {
        const int row0 = bm0 + wm + mi * 16 + grp;
        #pragma unroll
        for (int ni = 0; ni < 8; ni++) {
            const int col = bn0 + wn + ni * 8 + tig * 2;
            float2 v0, v1;
            v0.x = fmaxf(c[mi][ni][0] + bx[ni], 0.f);
            v0.y = fmaxf(c[mi][ni][1] + by[ni], 0.f);
            v1.x = fmaxf(c[mi][ni][2] + bx[ni], 0.f);
            v1.y = fmaxf(c[mi][ni][3] + by[ni], 0.f);
            *(float2*)&g_h[(size_t)row0 * HIDDEN + col]       = v0;
            *(float2*)&g_h[(size_t)(row0 + 8) * HIDDEN + col] = v1;
        }
    }
}

// ---------------------------------------------------------------------------
// W2 transpose (tiny)
// ---------------------------------------------------------------------------
__global__ void w2t_kernel(const float* __restrict__ W2) {
    const int i = blockIdx.x * 256 + (int)threadIdx.x;
    if (i < HIDDEN * OUT_DIM) {
        const int k = i / OUT_DIM, j = i % OUT_DIM;
        g_w2t[j][k] = W2[i];
    }
}

// ---------------------------------------------------------------------------
// fc2: warp-per-row (8 rows/CTA), pure shuffle reduction, no shared memory.
// ---------------------------------------------------------------------------
__global__ __launch_bounds__(256) void fc2_kernel(
    const float* __restrict__ b2, float* __restrict__ out)
{
    const int warp = (int)threadIdx.x >> 5, lane = (int)threadIdx.x & 31;
    const int row  = blockIdx.x * 8 + warp;

    float acc[OUT_DIM];
    #pragma unroll
    for (int j = 0; j < OUT_DIM; j++) acc[j] = 0.f;

    const float4* hv = (const float4*)(g_h + (size_t)row * HIDDEN);
    #pragma unroll 4
    for (int i = lane; i < HIDDEN / 4; i += 32) {
        const float4 h4 = hv[i];
        #pragma unroll
        for (int j = 0; j < OUT_DIM; j++) {
            const float4 w = *(const float4*)&g_w2t[j][i * 4];
            acc[j] += fmaf(h4.x, w.x, fmaf(h4.y, w.y, fmaf(h4.z, w.z, h4.w * w.w)));
        }
    }
    #pragma unroll
    for (int j = 0; j < OUT_DIM; j++)
        #pragma unroll
        for (int off = 16; off; off >>= 1)
            acc[j] += __shfl_xor_sync(0xffffffffu, acc[j], off);

    if (lane == 0) {
        #pragma unroll
        for (int j = 0; j < OUT_DIM; j++)
            out[(size_t)row * OUT_DIM + j] = acc[j] + __ldg(b2 + j);
    }
}

// ---------------------------------------------------------------------------
extern "C" void kernel_launch(void* const* d_in, const int* in_sizes, int n_in,
                              void* d_out, int out_size) {
    const float* x  = (const float*)d_in[0];   // [8192, 3072]
    const float* W1 = (const float*)d_in[1];   // [3072, 4096]
    const float* b1 = (const float*)d_in[2];   // [4096]
    const float* W2 = (const float*)d_in[3];   // [4096, 10]
    const float* b2 = (const float*)d_in[4];   // [10]
    float* out = (float*)d_out;                // [8192, 10]
    (void)in_sizes; (void)n_in; (void)out_size;

    cudaFuncSetAttribute(fc1_mma_kernel,
                         cudaFuncAttributeMaxDynamicSharedMemorySize, SMEM_TOTAL);

    xr_kernel<<<(BATCH * IN_DIM / 4 + 255) / 256, 256>>>(x);
    w1t_kernel<<<dim3(HIDDEN / 32, IN_DIM / 32), dim3(32, 8)>>>(W1);

    dim3 grid1(HIDDEN / BN, BATCH / BM);       // 32 x 32 = 1024 CTAs
    fc1_mma_kernel<<<grid1, 256, SMEM_TOTAL>>>(b1);

    w2t_kernel<<<(HIDDEN * OUT_DIM + 255) / 256, 256>>>(W2);
    fc2_kernel<<<BATCH / 8, 256>>>(b2, out);
}